// round 6
// baseline (speedup 1.0000x reference)
#include <cuda_runtime.h>
#include <cstdint>

#define NB 16
#define NL 1024
#define ND 512
#define NH 256
#define NK 4
#define NROWS (NB * NL)   // 16384

// ---------------- scratch (static device globals; no allocs) ----------------
__device__ float g_sel [NROWS * NK];     // softmax selections     (256 KB)
__device__ float g_uin [NROWS * NH];     // x @ W_B^T              (16 MB)
__device__ float g_invn[NROWS * NH];     // 1/norm per (row, j)    (16 MB)

// ---------------- helpers ----------------------------------------------------
__device__ __forceinline__ float fast_lg2(float x) {
    float r; asm("lg2.approx.f32 %0, %1;" : "=f"(r) : "f"(x)); return r;
}
__device__ __forceinline__ float fast_ex2(float x) {
    float r; asm("ex2.approx.f32 %0, %1;" : "=f"(r) : "f"(x)); return r;
}
__device__ __forceinline__ uint32_t smem_u32(const void* p) {
    uint32_t a;
    asm("{ .reg .u64 t; cvta.to.shared.u64 t, %1; cvt.u32.u64 %0, t; }"
        : "=r"(a) : "l"(p));
    return a;
}
__device__ __forceinline__ uint32_t mapa_u32(uint32_t a, uint32_t r) {
    uint32_t d;
    asm("mapa.shared::cluster.u32 %0, %1, %2;" : "=r"(d) : "r"(a), "r"(r));
    return d;
}

// ---------------- kernel 1: selection logits + softmax ----------------------
__global__ __launch_bounds__(256) void sel_kernel(
    const float* __restrict__ x, const float* __restrict__ Wsel,
    const float* __restrict__ bsel)
{
    __shared__ float Ws[NK * ND];
    for (int i = threadIdx.x; i < NK * ND; i += blockDim.x) Ws[i] = Wsel[i];
    __syncthreads();

    int w = threadIdx.x >> 5, l = threadIdx.x & 31;
    int row = blockIdx.x * 8 + w;
    const float* xr = x + row * ND;

    float p0 = 0.f, p1 = 0.f, p2 = 0.f, p3 = 0.f;
    for (int d = l; d < ND; d += 32) {
        float xv = xr[d];
        p0 += xv * Ws[d];
        p1 += xv * Ws[ND + d];
        p2 += xv * Ws[2 * ND + d];
        p3 += xv * Ws[3 * ND + d];
    }
#pragma unroll
    for (int o = 16; o > 0; o >>= 1) {
        p0 += __shfl_xor_sync(0xffffffffu, p0, o);
        p1 += __shfl_xor_sync(0xffffffffu, p1, o);
        p2 += __shfl_xor_sync(0xffffffffu, p2, o);
        p3 += __shfl_xor_sync(0xffffffffu, p3, o);
    }
    if (l == 0) {
        float l0 = p0 + bsel[0], l1 = p1 + bsel[1], l2 = p2 + bsel[2], l3 = p3 + bsel[3];
        float m = fmaxf(fmaxf(l0, l1), fmaxf(l2, l3));
        float e0 = __expf(l0 - m), e1 = __expf(l1 - m), e2 = __expf(l2 - m), e3 = __expf(l3 - m);
        float inv = 1.0f / (e0 + e1 + e2 + e3);
        float4 out = make_float4(e0 * inv, e1 * inv, e2 * inv, e3 * inv);
        *reinterpret_cast<float4*>(&g_sel[row * NK]) = out;
    }
}

// ---------------- kernel 2: u = x @ W_B^T  (M=16384, N=256, K=512) ----------
__global__ __launch_bounds__(256) void uin_kernel(
    const float* __restrict__ X, const float* __restrict__ Wb)
{
    __shared__ float Xs[16][64];
    __shared__ float Wt[16][64];
    int m0 = blockIdx.y * 64;
    int n0 = blockIdx.x * 64;
    int tid = threadIdx.x;
    int tx = tid & 15, ty = tid >> 4;
    int lr = tid >> 2, lq = tid & 3;

    float acc[4][4];
#pragma unroll
    for (int r = 0; r < 4; r++)
#pragma unroll
        for (int c = 0; c < 4; c++) acc[r][c] = 0.f;

    for (int k0 = 0; k0 < ND; k0 += 16) {
        float4 xv = *reinterpret_cast<const float4*>(&X [(m0 + lr) * ND + k0 + lq * 4]);
        float4 wv = *reinterpret_cast<const float4*>(&Wb[(n0 + lr) * ND + k0 + lq * 4]);
        __syncthreads();
        Xs[lq * 4 + 0][lr] = xv.x; Xs[lq * 4 + 1][lr] = xv.y;
        Xs[lq * 4 + 2][lr] = xv.z; Xs[lq * 4 + 3][lr] = xv.w;
        Wt[lq * 4 + 0][lr] = wv.x; Wt[lq * 4 + 1][lr] = wv.y;
        Wt[lq * 4 + 2][lr] = wv.z; Wt[lq * 4 + 3][lr] = wv.w;
        __syncthreads();
#pragma unroll
        for (int kk = 0; kk < 16; kk++) {
            float4 a = *reinterpret_cast<const float4*>(&Xs[kk][ty * 4]);
            float4 b = *reinterpret_cast<const float4*>(&Wt[kk][tx * 4]);
            acc[0][0] += a.x * b.x; acc[0][1] += a.x * b.y; acc[0][2] += a.x * b.z; acc[0][3] += a.x * b.w;
            acc[1][0] += a.y * b.x; acc[1][1] += a.y * b.y; acc[1][2] += a.y * b.z; acc[1][3] += a.y * b.w;
            acc[2][0] += a.z * b.x; acc[2][1] += a.z * b.y; acc[2][2] += a.z * b.z; acc[2][3] += a.z * b.w;
            acc[3][0] += a.w * b.x; acc[3][1] += a.w * b.y; acc[3][2] += a.w * b.z; acc[3][3] += a.w * b.w;
        }
    }
#pragma unroll
    for (int r = 0; r < 4; r++) {
        float4 o = make_float4(acc[r][0], acc[r][1], acc[r][2], acc[r][3]);
        *reinterpret_cast<float4*>(&g_uin[(m0 + ty * 4 + r) * NH + n0 + tx * 4]) = o;
    }
}

// ---------------- kernel 3: inv_norm pre-pass (register-resident A) ---------
__global__ __launch_bounds__(256, 3) void norm_kernel(const float* __restrict__ A)
{
    int jbase = blockIdx.x * 8;
    int w = threadIdx.x >> 5, l = threadIdx.x & 31;
    int j = jbase + w;

    float4 Ar[8];
#pragma unroll
    for (int r = 0; r < 8; r++)
        Ar[r] = reinterpret_cast<const float4*>(A)[(l + 32 * r) * NH + j];

    const int rows_per_blk = NROWS / 64;       // 256
    const int row0 = blockIdx.y * rows_per_blk;
    const float ninv = -1.0f / 1.2f;

    for (int row = row0; row < row0 + rows_per_blk; row += 2) {
        float4 sA = __ldg(reinterpret_cast<const float4*>(&g_sel[row * NK]));
        float4 sB = __ldg(reinterpret_cast<const float4*>(&g_sel[(row + 1) * NK]));
        float accA = 0.f, accB = 0.f;
#pragma unroll
        for (int r = 0; r < 8; r++) {
            float a = fmaf(sA.x, Ar[r].x, fmaf(sA.y, Ar[r].y,
                      fmaf(sA.z, Ar[r].z, sA.w * Ar[r].w)));
            float b = fmaf(sB.x, Ar[r].x, fmaf(sB.y, Ar[r].y,
                      fmaf(sB.z, Ar[r].z, sB.w * Ar[r].w)));
            accA += fast_ex2(0.6f * fast_lg2(a * a));
            accB += fast_ex2(0.6f * fast_lg2(b * b));
        }
#pragma unroll
        for (int o = 16; o > 0; o >>= 1) {
            accA += __shfl_xor_sync(0xffffffffu, accA, o);
            accB += __shfl_xor_sync(0xffffffffu, accB, o);
        }
        if (l == 0) {
            g_invn[row * NH + j]       = fast_ex2(fast_lg2(accA) * ninv);
            g_invn[(row + 1) * NH + j] = fast_ex2(fast_lg2(accB) * ninv);
        }
    }
}

// ---------------- kernel 4: scan, decentralized warps ----------------------
// Cluster = batch. CTA rank owns j (and output rows) in [rank*32, rank*32+32).
// Thread: global row i = tid>>1, half = tid&1 covers 16 local j's. Warp w's
// 16 rows all belong to owner CTA (w>>1). Per-lane state: lane l of EVERY
// warp holds h / y / u / inv for local row l (redundant across warps — free,
// removes warp0 serialization entirely).
// Per step: shfl-fed matvec (amix preloaded) -> pair reduce -> even lanes
// st.async row partial to owner pbuf[t&1] (+tx on owner mbar) -> amix(t+1)
// in flight shadow -> ALL warps try_wait(parity) -> each warp sums pbuf
// lane-parallel -> h,y updated in regs; warp0 stores out; tid0 posts
// expect_tx for t+2 BEFORE the single __syncthreads (pbuf reuse guard:
// remote t+2 stores require remote wait(t+1) require our t+1 stores which
// are gated by this sync).
__global__ __launch_bounds__(512, 1) __cluster_dims__(8, 1, 1)
void scan_kernel(const float* __restrict__ A, float* __restrict__ out)
{
    __shared__ float pbuf[2][8][32];
    __shared__ __align__(8) unsigned long long mbar[2];

    int tid = threadIdx.x;
    uint32_t rank;
    asm("mov.u32 %0, %%cluster_ctarank;" : "=r"(rank));
    int b = blockIdx.x >> 3;
    int jbase = (int)rank * 32;
    int i = tid >> 1, half = tid & 1;
    int w = tid >> 5, lane = tid & 31;

    float4 Areg[16];
#pragma unroll
    for (int q = 0; q < 16; q++)
        Areg[q] = reinterpret_cast<const float4*>(A)[i * NH + jbase + half * 16 + q];

    // mbarrier setup: count=1 (tid0's arrive.expect_tx), tx=1024 B/phase
    uint32_t mbar_s = smem_u32(mbar);
    if (tid == 0) {
        asm volatile("mbarrier.init.shared.b64 [%0], 1;" :: "r"(mbar_s) : "memory");
        asm volatile("mbarrier.init.shared.b64 [%0], 1;" :: "r"(mbar_s + 8) : "memory");
    }
    __syncthreads();
    if (tid == 0) {
        asm volatile("mbarrier.arrive.expect_tx.shared.b64 _, [%0], 1024;" :: "r"(mbar_s) : "memory");
        asm volatile("mbarrier.arrive.expect_tx.shared.b64 _, [%0], 1024;" :: "r"(mbar_s + 8) : "memory");
    }
    __syncthreads();
    asm volatile("barrier.cluster.arrive.aligned;" ::: "memory");
    asm volatile("barrier.cluster.wait.aligned;"  ::: "memory");

    // remote address for this thread's row partial (owner CTA = w>>1)
    uint32_t dst = (uint32_t)(w >> 1);
    uint32_t slot = rank * 32u + (uint32_t)(((w & 1) << 4) | (lane >> 1));
    uint32_t laddr = smem_u32(pbuf) + slot * 4u;
    uint32_t raddr0 = mapa_u32(laddr, dst);
    uint32_t raddr1 = raddr0 + 8u * 32u * 4u;
    uint32_t rmbar0 = mapa_u32(mbar_s, dst);
    uint32_t rmbar1 = rmbar0 + 8u;

    const int rowbase = b * NL;
    // per-lane state (every warp holds the full owned-32 vector, lane l = local row l)
    float u_cur = __ldg(&g_uin [rowbase * NH + jbase + lane]);
    float y = 0.f;                                    // h0 = 0
    float4 s_cur = __ldg(reinterpret_cast<const float4*>(&g_sel[rowbase * NK]));

    float amix[16];
#pragma unroll
    for (int q = 0; q < 16; q++)
        amix[q] = fmaf(s_cur.x, Areg[q].x, fmaf(s_cur.y, Areg[q].y,
                  fmaf(s_cur.z, Areg[q].z, s_cur.w * Areg[q].w)));

    for (int t = 0; t < NL; t++) {
        const int row = rowbase + t;
        const int rown = row + (t < NL - 1 ? 1 : 0);

        // prefetch next-step row data (consumed after the wait)
        float4 s_nxt  = __ldg(reinterpret_cast<const float4*>(&g_sel[rown * NK]));
        float inv_nxt = __ldg(&g_invn[rown * NH + jbase + lane]);
        float u_nxt   = __ldg(&g_uin [rown * NH + jbase + lane]);

        // matvec: y_j pulled from lane j via shfl; two acc chains for ILP
        float acc0 = 0.f, acc1 = 0.f;
#pragma unroll
        for (int q = 0; q < 16; q += 2) {
            float y0 = __shfl_sync(0xffffffffu, y, half * 16 + q);
            float y1 = __shfl_sync(0xffffffffu, y, half * 16 + q + 1);
            acc0 = fmaf(amix[q], y0, acc0);
            acc1 = fmaf(amix[q + 1], y1, acc1);
        }
        float acc = acc0 + acc1;
        acc += __shfl_xor_sync(0xffffffffu, acc, 1);

        if (half == 0) {
            uint32_t ra = (t & 1) ? raddr1 : raddr0;
            uint32_t rm = (t & 1) ? rmbar1 : rmbar0;
            asm volatile(
                "st.async.shared::cluster.mbarrier::complete_tx::bytes.b32 [%0], %1, [%2];"
                :: "r"(ra), "r"(__float_as_uint(acc)), "r"(rm) : "memory");
        }

        // hide DSMEM flight: amix for t+1
#pragma unroll
        for (int q = 0; q < 16; q++)
            amix[q] = fmaf(s_nxt.x, Areg[q].x, fmaf(s_nxt.y, Areg[q].y,
                      fmaf(s_nxt.z, Areg[q].z, s_nxt.w * Areg[q].w)));

        // every warp waits on the phase itself
        {
            uint32_t mb = mbar_s + (uint32_t)((t & 1) * 8);
            uint32_t ph = (uint32_t)((t >> 1) & 1);
            asm volatile(
                "{\n\t.reg .pred p;\n"
                "WL%=:\n\t"
                "mbarrier.try_wait.parity.acquire.cluster.shared::cta.b64 p, [%0], %1;\n\t"
                "@!p bra WL%=;\n\t}"
                :: "r"(mb), "r"(ph) : "memory");
        }

        // lane-parallel consume: h_l = u_l + sum of 8 partials (pairwise tree)
        {
            const float* pb = &pbuf[t & 1][0][lane];
            float a0 = pb[0]   + pb[32];
            float a1 = pb[64]  + pb[96];
            float a2 = pb[128] + pb[160];
            float a3 = pb[192] + pb[224];
            float hv = u_cur + ((a0 + a1) + (a2 + a3));
            if (w == 0) out[row * NH + jbase + lane] = hv;
            y = hv * inv_nxt;            // y for step t+1
        }
        u_cur = u_nxt;

        // expect for t+2 posted BEFORE the sync (provably precedes any t+2 tx)
        if (tid == 0 && t + 2 < NL) {
            uint32_t mb = mbar_s + (uint32_t)((t & 1) * 8);
            asm volatile("mbarrier.arrive.expect_tx.shared.b64 _, [%0], 1024;"
                         :: "r"(mb) : "memory");
        }
        __syncthreads();                 // pbuf[t&1] reuse guard
    }

    asm volatile("barrier.cluster.arrive.aligned;" ::: "memory");
    asm volatile("barrier.cluster.wait.aligned;"  ::: "memory");
}

// ---------------- launch ----------------------------------------------------
extern "C" void kernel_launch(void* const* d_in, const int* in_sizes, int n_in,
                              void* d_out, int out_size)
{
    const float* x     = (const float*)d_in[0];   // (16,1024,512)
    const float* Wsel  = (const float*)d_in[1];   // (4,512)
    const float* bsel  = (const float*)d_in[2];   // (4,)
    const float* Wb    = (const float*)d_in[3];   // (256,512)
    const float* Adict = (const float*)d_in[4];   // (256,256,4)
    float* out = (float*)d_out;                   // (16,1024,256)

    sel_kernel<<<NROWS / 8, 256>>>(x, Wsel, bsel);
    uin_kernel<<<dim3(NH / 64, NROWS / 64), 256>>>(x, Wb);
    norm_kernel<<<dim3(32, 64), 256>>>(Adict);
    scan_kernel<<<NB * 8, 512>>>(Adict, out);
}

// round 7
// speedup vs baseline: 1.2795x; 1.2795x over previous
#include <cuda_runtime.h>
#include <cstdint>

#define NB 16
#define NL 1024
#define ND 512
#define NH 256
#define NK 4
#define NROWS (NB * NL)   // 16384

// ---------------- scratch (static device globals; no allocs) ----------------
__device__ float g_sel [NROWS * NK];     // softmax selections     (256 KB)
__device__ float g_uin [NROWS * NH];     // x @ W_B^T              (16 MB)
__device__ float g_invn[NROWS * NH];     // 1/norm per (row, j)    (16 MB)

// ---------------- helpers ----------------------------------------------------
__device__ __forceinline__ float fast_lg2(float x) {
    float r; asm("lg2.approx.f32 %0, %1;" : "=f"(r) : "f"(x)); return r;
}
__device__ __forceinline__ float fast_ex2(float x) {
    float r; asm("ex2.approx.f32 %0, %1;" : "=f"(r) : "f"(x)); return r;
}
__device__ __forceinline__ uint32_t smem_u32(const void* p) {
    uint32_t a;
    asm("{ .reg .u64 t; cvta.to.shared.u64 t, %1; cvt.u32.u64 %0, t; }"
        : "=r"(a) : "l"(p));
    return a;
}
__device__ __forceinline__ uint32_t mapa_u32(uint32_t a, uint32_t r) {
    uint32_t d;
    asm("mapa.shared::cluster.u32 %0, %1, %2;" : "=r"(d) : "r"(a), "r"(r));
    return d;
}
__device__ __forceinline__ void mbar_wait(uint32_t mb, uint32_t ph) {
    asm volatile(
        "{\n\t.reg .pred p;\n"
        "WL%=:\n\t"
        "mbarrier.try_wait.parity.acquire.cluster.shared::cta.b64 p, [%0], %1;\n\t"
        "@!p bra WL%=;\n\t}"
        :: "r"(mb), "r"(ph) : "memory");
}

// ---------------- kernel 1: selection logits + softmax ----------------------
__global__ __launch_bounds__(256) void sel_kernel(
    const float* __restrict__ x, const float* __restrict__ Wsel,
    const float* __restrict__ bsel)
{
    __shared__ float Ws[NK * ND];
    for (int i = threadIdx.x; i < NK * ND; i += blockDim.x) Ws[i] = Wsel[i];
    __syncthreads();

    int w = threadIdx.x >> 5, l = threadIdx.x & 31;
    int row = blockIdx.x * 8 + w;
    const float* xr = x + row * ND;

    float p0 = 0.f, p1 = 0.f, p2 = 0.f, p3 = 0.f;
    for (int d = l; d < ND; d += 32) {
        float xv = xr[d];
        p0 += xv * Ws[d];
        p1 += xv * Ws[ND + d];
        p2 += xv * Ws[2 * ND + d];
        p3 += xv * Ws[3 * ND + d];
    }
#pragma unroll
    for (int o = 16; o > 0; o >>= 1) {
        p0 += __shfl_xor_sync(0xffffffffu, p0, o);
        p1 += __shfl_xor_sync(0xffffffffu, p1, o);
        p2 += __shfl_xor_sync(0xffffffffu, p2, o);
        p3 += __shfl_xor_sync(0xffffffffu, p3, o);
    }
    if (l == 0) {
        float l0 = p0 + bsel[0], l1 = p1 + bsel[1], l2 = p2 + bsel[2], l3 = p3 + bsel[3];
        float m = fmaxf(fmaxf(l0, l1), fmaxf(l2, l3));
        float e0 = __expf(l0 - m), e1 = __expf(l1 - m), e2 = __expf(l2 - m), e3 = __expf(l3 - m);
        float inv = 1.0f / (e0 + e1 + e2 + e3);
        float4 out = make_float4(e0 * inv, e1 * inv, e2 * inv, e3 * inv);
        *reinterpret_cast<float4*>(&g_sel[row * NK]) = out;
    }
}

// ---------------- kernel 2: u = x @ W_B^T  (M=16384, N=256, K=512) ----------
__global__ __launch_bounds__(256) void uin_kernel(
    const float* __restrict__ X, const float* __restrict__ Wb)
{
    __shared__ float Xs[16][64];
    __shared__ float Wt[16][64];
    int m0 = blockIdx.y * 64;
    int n0 = blockIdx.x * 64;
    int tid = threadIdx.x;
    int tx = tid & 15, ty = tid >> 4;
    int lr = tid >> 2, lq = tid & 3;

    float acc[4][4];
#pragma unroll
    for (int r = 0; r < 4; r++)
#pragma unroll
        for (int c = 0; c < 4; c++) acc[r][c] = 0.f;

    for (int k0 = 0; k0 < ND; k0 += 16) {
        float4 xv = *reinterpret_cast<const float4*>(&X [(m0 + lr) * ND + k0 + lq * 4]);
        float4 wv = *reinterpret_cast<const float4*>(&Wb[(n0 + lr) * ND + k0 + lq * 4]);
        __syncthreads();
        Xs[lq * 4 + 0][lr] = xv.x; Xs[lq * 4 + 1][lr] = xv.y;
        Xs[lq * 4 + 2][lr] = xv.z; Xs[lq * 4 + 3][lr] = xv.w;
        Wt[lq * 4 + 0][lr] = wv.x; Wt[lq * 4 + 1][lr] = wv.y;
        Wt[lq * 4 + 2][lr] = wv.z; Wt[lq * 4 + 3][lr] = wv.w;
        __syncthreads();
#pragma unroll
        for (int kk = 0; kk < 16; kk++) {
            float4 a = *reinterpret_cast<const float4*>(&Xs[kk][ty * 4]);
            float4 b = *reinterpret_cast<const float4*>(&Wt[kk][tx * 4]);
            acc[0][0] += a.x * b.x; acc[0][1] += a.x * b.y; acc[0][2] += a.x * b.z; acc[0][3] += a.x * b.w;
            acc[1][0] += a.y * b.x; acc[1][1] += a.y * b.y; acc[1][2] += a.y * b.z; acc[1][3] += a.y * b.w;
            acc[2][0] += a.z * b.x; acc[2][1] += a.z * b.y; acc[2][2] += a.z * b.z; acc[2][3] += a.z * b.w;
            acc[3][0] += a.w * b.x; acc[3][1] += a.w * b.y; acc[3][2] += a.w * b.z; acc[3][3] += a.w * b.w;
        }
    }
#pragma unroll
    for (int r = 0; r < 4; r++) {
        float4 o = make_float4(acc[r][0], acc[r][1], acc[r][2], acc[r][3]);
        *reinterpret_cast<float4*>(&g_uin[(m0 + ty * 4 + r) * NH + n0 + tx * 4]) = o;
    }
}

// ---------------- kernel 3: inv_norm pre-pass (register-resident A) ---------
__global__ __launch_bounds__(256, 3) void norm_kernel(const float* __restrict__ A)
{
    int jbase = blockIdx.x * 8;
    int w = threadIdx.x >> 5, l = threadIdx.x & 31;
    int j = jbase + w;

    float4 Ar[8];
#pragma unroll
    for (int r = 0; r < 8; r++)
        Ar[r] = reinterpret_cast<const float4*>(A)[(l + 32 * r) * NH + j];

    const int rows_per_blk = NROWS / 64;       // 256
    const int row0 = blockIdx.y * rows_per_blk;
    const float ninv = -1.0f / 1.2f;

    for (int row = row0; row < row0 + rows_per_blk; row += 2) {
        float4 sA = __ldg(reinterpret_cast<const float4*>(&g_sel[row * NK]));
        float4 sB = __ldg(reinterpret_cast<const float4*>(&g_sel[(row + 1) * NK]));
        float accA = 0.f, accB = 0.f;
#pragma unroll
        for (int r = 0; r < 8; r++) {
            float a = fmaf(sA.x, Ar[r].x, fmaf(sA.y, Ar[r].y,
                      fmaf(sA.z, Ar[r].z, sA.w * Ar[r].w)));
            float b = fmaf(sB.x, Ar[r].x, fmaf(sB.y, Ar[r].y,
                      fmaf(sB.z, Ar[r].z, sB.w * Ar[r].w)));
            accA += fast_ex2(0.6f * fast_lg2(a * a));
            accB += fast_ex2(0.6f * fast_lg2(b * b));
        }
#pragma unroll
        for (int o = 16; o > 0; o >>= 1) {
            accA += __shfl_xor_sync(0xffffffffu, accA, o);
            accB += __shfl_xor_sync(0xffffffffu, accB, o);
        }
        if (l == 0) {
            g_invn[row * NH + j]       = fast_ex2(fast_lg2(accA) * ninv);
            g_invn[(row + 1) * NH + j] = fast_ex2(fast_lg2(accB) * ninv);
        }
    }
}

// ---------------- kernel 4: scan, 2 batches per cluster (R5 base) -----------
// 8 clusters x 8 CTAs; cluster c runs batches 2c and 2c+1 interleaved. CTA
// rank owns j (and h rows) [rank*32, rank*32+32) for BOTH batches; the A-slice
// registers are shared. Per iteration (one step of each batch):
//   warp0 writes y_sm[2][32]; sync; all warps matvec+pair-reduce+st.async for
//   batch0 then batch1 (batch0's DSMEM flight hides under batch1 compute and
//   the amix(t+1) recompute); warp0 waits batch0 mbar, consumes, posts
//   expect(t+2), then batch1 likewise. One __syncthreads per iteration (top).
// tx per mbar per phase = 8 CTAs x 32 rows x 4B = 1024B. expect(t+2) is posted
// in tail(t), before any producer can issue a t+2 store (producer t+2 stores
// are gated by its top-sync(t+1) <- its tail(t+1) wait <- our t+1 stores <-
// our top-sync(t+1) <- our tail(t) completing). pbuf reuse is guarded by the
// same chain.
__global__ __launch_bounds__(512, 1) __cluster_dims__(8, 1, 1)
void scan_kernel(const float* __restrict__ A, float* __restrict__ out)
{
    __shared__ float y_sm[2][32];
    __shared__ float pbuf[2][2][8][32];                 // [parity][batch][src][row]
    __shared__ __align__(8) unsigned long long mbar[2][2];  // [parity][batch]

    int tid = threadIdx.x;
    uint32_t rank;
    asm("mov.u32 %0, %%cluster_ctarank;" : "=r"(rank));
    int c = blockIdx.x >> 3;                 // cluster id -> batches 2c, 2c+1
    int jbase = (int)rank * 32;
    int i = tid >> 1, half = tid & 1;

    float4 Areg[16];
#pragma unroll
    for (int q = 0; q < 16; q++)
        Areg[q] = reinterpret_cast<const float4*>(A)[i * NH + jbase + half * 16 + q];

    uint32_t mbar_s = smem_u32(mbar);
    if (tid == 0) {
#pragma unroll
        for (int m = 0; m < 4; m++)
            asm volatile("mbarrier.init.shared.b64 [%0], 1;"
                         :: "r"(mbar_s + m * 8) : "memory");
    }
    __syncthreads();
    if (tid == 0) {
#pragma unroll
        for (int m = 0; m < 4; m++)
            asm volatile("mbarrier.arrive.expect_tx.shared.b64 _, [%0], 1024;"
                         :: "r"(mbar_s + m * 8) : "memory");
    }
    __syncthreads();
    asm volatile("barrier.cluster.arrive.aligned;" ::: "memory");
    asm volatile("barrier.cluster.wait.aligned;"  ::: "memory");

    // remote addresses (owner CTA = i>>5); [parity][batch] strides in bytes
    uint32_t dst = (uint32_t)(i >> 5);
    uint32_t lbase = smem_u32(pbuf) + (rank * 32u + (uint32_t)(i & 31)) * 4u;
    uint32_t raddr = mapa_u32(lbase, dst);   // parity stride 2048B, batch stride 1024B
    uint32_t rmbar = mapa_u32(mbar_s, dst);  // parity stride 16B,   batch stride 8B

    const int row0base = (2 * c) * NL;
    const int row1base = (2 * c + 1) * NL;

    float4 s0 = __ldg(reinterpret_cast<const float4*>(&g_sel[row0base * NK]));
    float4 s1 = __ldg(reinterpret_cast<const float4*>(&g_sel[row1base * NK]));
    float inv0 = 0.f, u0 = 0.f, h0 = 0.f;
    float inv1 = 0.f, u1 = 0.f, h1 = 0.f;
    if (tid < 32) {
        inv0 = __ldg(&g_invn[row0base * NH + jbase + tid]);
        u0   = __ldg(&g_uin [row0base * NH + jbase + tid]);
        inv1 = __ldg(&g_invn[row1base * NH + jbase + tid]);
        u1   = __ldg(&g_uin [row1base * NH + jbase + tid]);
    }

    float amix0[16], amix1[16];
#pragma unroll
    for (int q = 0; q < 16; q++) {
        amix0[q] = fmaf(s0.x, Areg[q].x, fmaf(s0.y, Areg[q].y,
                   fmaf(s0.z, Areg[q].z, s0.w * Areg[q].w)));
        amix1[q] = fmaf(s1.x, Areg[q].x, fmaf(s1.y, Areg[q].y,
                   fmaf(s1.z, Areg[q].z, s1.w * Areg[q].w)));
    }

    for (int t = 0; t < NL; t++) {
        const int row0 = row0base + t;
        const int row1 = row1base + t;
        if (tid < 32) {
            y_sm[0][tid] = h0 * inv0;
            y_sm[1][tid] = h1 * inv1;
        }
        __syncthreads();

        // prefetch next-step row data
        const int d = (t < NL - 1) ? 1 : 0;
        float4 s_n0 = __ldg(reinterpret_cast<const float4*>(&g_sel[(row0 + d) * NK]));
        float4 s_n1 = __ldg(reinterpret_cast<const float4*>(&g_sel[(row1 + d) * NK]));
        float inv_n0 = 0.f, u_n0 = 0.f, inv_n1 = 0.f, u_n1 = 0.f;
        if (tid < 32) {
            inv_n0 = __ldg(&g_invn[(row0 + d) * NH + jbase + tid]);
            u_n0   = __ldg(&g_uin [(row0 + d) * NH + jbase + tid]);
            inv_n1 = __ldg(&g_invn[(row1 + d) * NH + jbase + tid]);
            u_n1   = __ldg(&g_uin [(row1 + d) * NH + jbase + tid]);
        }

        const uint32_t poff = (uint32_t)(t & 1);

        // ---- batch 0: matvec + store ----
        {
            float a0 = 0.f, a1 = 0.f;
#pragma unroll
            for (int q = 0; q < 16; q += 2) {
                a0 = fmaf(amix0[q],     y_sm[0][half * 16 + q],     a0);
                a1 = fmaf(amix0[q + 1], y_sm[0][half * 16 + q + 1], a1);
            }
            float acc = a0 + a1;
            acc += __shfl_xor_sync(0xffffffffu, acc, 1);
            if (half == 0) {
                asm volatile(
                    "st.async.shared::cluster.mbarrier::complete_tx::bytes.b32 [%0], %1, [%2];"
                    :: "r"(raddr + poff * 2048u), "r"(__float_as_uint(acc)),
                       "r"(rmbar + poff * 16u) : "memory");
            }
        }
        // ---- batch 1: matvec + store (hides batch0 flight) ----
        {
            float a0 = 0.f, a1 = 0.f;
#pragma unroll
            for (int q = 0; q < 16; q += 2) {
                a0 = fmaf(amix1[q],     y_sm[1][half * 16 + q],     a0);
                a1 = fmaf(amix1[q + 1], y_sm[1][half * 16 + q + 1], a1);
            }
            float acc = a0 + a1;
            acc += __shfl_xor_sync(0xffffffffu, acc, 1);
            if (half == 0) {
                asm volatile(
                    "st.async.shared::cluster.mbarrier::complete_tx::bytes.b32 [%0], %1, [%2];"
                    :: "r"(raddr + poff * 2048u + 1024u), "r"(__float_as_uint(acc)),
                       "r"(rmbar + poff * 16u + 8u) : "memory");
            }
        }

        // hide DSMEM flight further: amix for t+1, both batches
#pragma unroll
        for (int q = 0; q < 16; q++) {
            amix0[q] = fmaf(s_n0.x, Areg[q].x, fmaf(s_n0.y, Areg[q].y,
                       fmaf(s_n0.z, Areg[q].z, s_n0.w * Areg[q].w)));
            amix1[q] = fmaf(s_n1.x, Areg[q].x, fmaf(s_n1.y, Areg[q].y,
                       fmaf(s_n1.z, Areg[q].z, s_n1.w * Areg[q].w)));
        }

        if (tid < 32) {
            const uint32_t ph = (uint32_t)((t >> 1) & 1);
            // ---- batch 0 tail ----
            mbar_wait(mbar_s + poff * 16u, ph);
            if (tid == 0 && t + 2 < NL)
                asm volatile("mbarrier.arrive.expect_tx.shared.b64 _, [%0], 1024;"
                             :: "r"(mbar_s + poff * 16u) : "memory");
            {
                const float* pb = &pbuf[poff][0][0][tid];
                float b0 = pb[0]   + pb[32];
                float b1 = pb[64]  + pb[96];
                float b2 = pb[128] + pb[160];
                float b3 = pb[192] + pb[224];
                float hv = u0 + ((b0 + b1) + (b2 + b3));
                out[row0 * NH + jbase + tid] = hv;
                h0 = hv; inv0 = inv_n0; u0 = u_n0;
            }
            // ---- batch 1 tail ----
            mbar_wait(mbar_s + poff * 16u + 8u, ph);
            if (tid == 0 && t + 2 < NL)
                asm volatile("mbarrier.arrive.expect_tx.shared.b64 _, [%0], 1024;"
                             :: "r"(mbar_s + poff * 16u + 8u) : "memory");
            {
                const float* pb = &pbuf[poff][1][0][tid];
                float b0 = pb[0]   + pb[32];
                float b1 = pb[64]  + pb[96];
                float b2 = pb[128] + pb[160];
                float b3 = pb[192] + pb[224];
                float hv = u1 + ((b0 + b1) + (b2 + b3));
                out[row1 * NH + jbase + tid] = hv;
                h1 = hv; inv1 = inv_n1; u1 = u_n1;
            }
        }
    }

    asm volatile("barrier.cluster.arrive.aligned;" ::: "memory");
    asm volatile("barrier.cluster.wait.aligned;"  ::: "memory");
}

// ---------------- launch ----------------------------------------------------
extern "C" void kernel_launch(void* const* d_in, const int* in_sizes, int n_in,
                              void* d_out, int out_size)
{
    const float* x     = (const float*)d_in[0];   // (16,1024,512)
    const float* Wsel  = (const float*)d_in[1];   // (4,512)
    const float* bsel  = (const float*)d_in[2];   // (4,)
    const float* Wb    = (const float*)d_in[3];   // (256,512)
    const float* Adict = (const float*)d_in[4];   // (256,256,4)
    float* out = (float*)d_out;                   // (16,1024,256)

    sel_kernel<<<NROWS / 8, 256>>>(x, Wsel, bsel);
    uin_kernel<<<dim3(NH / 64, NROWS / 64), 256>>>(x, Wb);
    norm_kernel<<<dim3(32, 64), 256>>>(Adict);
    scan_kernel<<<(NB / 2) * 8, 512>>>(Adict, out);
}